// round 3
// baseline (speedup 1.0000x reference)
#include <cuda_runtime.h>
#include <cstdint>

// ---------------------------------------------------------------------------
// QuantumLayer: state confined to indices {0,1}; bulk = threefry2x32
// (partitionable) + XLA erfinv noise, then per-row normalization.
// K1: grid=1024 x 256thr, 8 elems/thread -> writes |z|^2 + per-block partials.
//     Single full-residency wave (no 2-wave tail, higher occupancy).
// K2: grid=256 x 1024thr -> rinv per row, out = sqrt(m2) * rinv (BW-bound,
//     absorbs the 2M sqrts for free).
// ---------------------------------------------------------------------------

__device__ float g_partials[1024];

// ----------------------------- complex helpers -----------------------------
__device__ __forceinline__ float2 cmul(float2 a, float2 b) {
    return make_float2(a.x * b.x - a.y * b.y, a.x * b.y + a.y * b.x);
}
__device__ __forceinline__ float2 cadd(float2 a, float2 b) {
    return make_float2(a.x + b.x, a.y + b.y);
}

struct C2x2 { float2 m00, m01, m10, m11; };

__device__ __forceinline__ C2x2 mmul(const C2x2& A, const C2x2& B) {  // A*B
    C2x2 R;
    R.m00 = cadd(cmul(A.m00, B.m00), cmul(A.m01, B.m10));
    R.m01 = cadd(cmul(A.m00, B.m01), cmul(A.m01, B.m11));
    R.m10 = cadd(cmul(A.m10, B.m00), cmul(A.m11, B.m10));
    R.m11 = cadd(cmul(A.m10, B.m01), cmul(A.m11, B.m11));
    return R;
}

__device__ __forceinline__ float2 shf2(float2 v, int off) {
    return make_float2(__shfl_down_sync(0xFFFFFFFFu, v.x, off),
                       __shfl_down_sync(0xFFFFFFFFu, v.y, off));
}
__device__ __forceinline__ C2x2 shfm(const C2x2& P, int off) {
    C2x2 Q;
    Q.m00 = shf2(P.m00, off); Q.m01 = shf2(P.m01, off);
    Q.m10 = shf2(P.m10, off); Q.m11 = shf2(P.m11, off);
    return Q;
}

// ----------------------------- threefry-2x32 -------------------------------
__device__ __forceinline__ uint2 threefry2x32(uint32_t k0, uint32_t k1,
                                              uint32_t x0, uint32_t x1) {
    uint32_t ks2 = 0x1BD11BDAu ^ k0 ^ k1;
#define TF_R(r) { x0 += x1; x1 = __funnelshift_l(x1, x1, (r)); x1 ^= x0; }
    x0 += k0;  x1 += k1;
    TF_R(13) TF_R(15) TF_R(26) TF_R(6)
    x0 += k1;  x1 += ks2 + 1u;
    TF_R(17) TF_R(29) TF_R(16) TF_R(24)
    x0 += ks2; x1 += k0 + 2u;
    TF_R(13) TF_R(15) TF_R(26) TF_R(6)
    x0 += k0;  x1 += k1 + 3u;
    TF_R(17) TF_R(29) TF_R(16) TF_R(24)
    x0 += k1;  x1 += ks2 + 4u;
    TF_R(13) TF_R(15) TF_R(26) TF_R(6)
    x0 += ks2; x1 += k0 + 5u;
#undef TF_R
    return make_uint2(x0, x1);
}

// ------------------- XLA erf_inv (f32), fast log variant -------------------
__device__ __forceinline__ float xla_erfinv_fast(float x) {
    float w = -__logf(fmaf(x, -x, 1.0f));
    float p;
    if (w < 5.0f) {
        w -= 2.5f;
        p = 2.81022636e-08f;
        p = fmaf(p, w, 3.43273939e-07f);
        p = fmaf(p, w, -3.5233877e-06f);
        p = fmaf(p, w, -4.39150654e-06f);
        p = fmaf(p, w, 0.00021858087f);
        p = fmaf(p, w, -0.00125372503f);
        p = fmaf(p, w, -0.00417768164f);
        p = fmaf(p, w, 0.246640727f);
        p = fmaf(p, w, 1.50140941f);
    } else {
        w = sqrtf(w) - 3.0f;
        p = -0.000200214257f;
        p = fmaf(p, w, 0.000100950558f);
        p = fmaf(p, w, 0.00134934322f);
        p = fmaf(p, w, -0.00367342844f);
        p = fmaf(p, w, 0.00573950773f);
        p = fmaf(p, w, -0.0076224613f);
        p = fmaf(p, w, 0.00943887047f);
        p = fmaf(p, w, 1.00167406f);
        p = fmaf(p, w, 2.83297682f);
    }
    return p * x;
}

// one noise stream element: bits -> u -> 0.01 * erfinv(u)
__device__ __forceinline__ float noise_val(uint32_t k0, uint32_t k1, uint32_t j) {
    const float LO = -0.99999994039535522461f;   // nextafter(-1, 0)
    uint2 b = threefry2x32(k0, k1, 0u, j);
    uint32_t bits = b.x ^ b.y;
    float F = __uint_as_float((bits >> 9) | 0x3f800000u);     // [1, 2)
    float u = fmaxf(LO, fmaf(F, 2.0f, LO - 2.0f));            // [LO, 1)
    return xla_erfinv_fast(u) * 0.01f;
}

// ---------------------------------------------------------------------------
// K1: noise + |z|^2. grid=1024 (256 rows x 4 segs), block=256, 8 elems/thread.
// ---------------------------------------------------------------------------
__global__ __launch_bounds__(256) void k_noise(
    const float* __restrict__ rx, const float* __restrict__ ry,
    const float* __restrict__ rz, float* __restrict__ out,
    uint32_t kre0, uint32_t kre1, uint32_t kim0, uint32_t kim1) {

    const int t   = threadIdx.x;
    const int bid = blockIdx.x;
    const int row = bid >> 2;
    const int seg = bid & 3;

    // ---- warp 0 of seg==0 blocks: 78-gate 2x2 product (only lanes 0/1 use it)
    float2 amp = {0.f, 0.f};
    if (seg == 0 && t < 32) {
        const int lane = t;
        const int lo = (lane * 78) >> 5;
        const int hi = ((lane + 1) * 78) >> 5;
        C2x2 P;
        P.m00 = {1.f, 0.f}; P.m01 = {0.f, 0.f};
        P.m10 = {0.f, 0.f}; P.m11 = {1.f, 0.f};
        for (int g = lo; g < hi; ++g) {
            float a; int axis;
            if (g < 26)      { a = __ldg(rx + g);      axis = 0; }
            else if (g < 52) { a = __ldg(ry + g - 26); axis = 1; }
            else             { a = __ldg(rz + g - 52); axis = 2; }
            float s, c;
            sincosf(0.5f * a, &s, &c);
            float2 e00, e01, e10, e11;
            if (axis == 0) {        // rx
                e00 = {c, 0.f}; e01 = {0.f, -s}; e10 = {0.f, -s}; e11 = {c, 0.f};
            } else if (axis == 1) { // ry
                e00 = {c, 0.f}; e01 = {-s, 0.f}; e10 = {s, 0.f};  e11 = {c, 0.f};
            } else {                // rz
                e00 = {c, -s};  e01 = {0.f, 0.f}; e10 = {0.f, 0.f}; e11 = {c, s};
            }
            // fold the reference's in-place aliasing bug
            C2x2 E;
            E.m00 = e00;
            E.m01 = e01;
            E.m10 = cmul(e10, e00);
            E.m11 = cadd(cmul(e10, e01), e11);
            P = mmul(E, P);
        }
        #pragma unroll
        for (int off = 1; off < 32; off <<= 1) {
            C2x2 Q = shfm(P, off);
            if ((lane & (2 * off - 1)) == 0) P = mmul(Q, P);
        }
        // lane0 -> amp at d=0 (m00), lane1 -> amp at d=1 (m10)
        float2 a0, a1;
        a0.x = __shfl_sync(0xFFFFFFFFu, P.m00.x, 0);
        a0.y = __shfl_sync(0xFFFFFFFFu, P.m00.y, 0);
        a1.x = __shfl_sync(0xFFFFFFFFu, P.m10.x, 0);
        a1.y = __shfl_sync(0xFFFFFFFFu, P.m10.y, 0);
        if (lane == 0) amp = a0;
        if (lane == 1) amp = a1;
    }

    const uint32_t base = (uint32_t)(row * 8192 + seg * 2048 + t);
    float local = 0.0f;

    // ---- k = 0 peeled: amp registers die here ----
    {
        const uint32_t j = base;
        float re = noise_val(kre0, kre1, j);
        float im = noise_val(kim0, kim1, j);
        if (seg == 0 && t < 2) { re += amp.x; im += amp.y; }
        float m2 = fmaf(re, re, im * im);
        local += m2;
        out[j] = m2;
    }
#pragma unroll
    for (int k = 1; k < 8; k++) {
        const uint32_t j = base + k * 256;
        float re = noise_val(kre0, kre1, j);
        float im = noise_val(kim0, kim1, j);
        float m2 = fmaf(re, re, im * im);
        local += m2;
        out[j] = m2;
    }

    // ---- block reduction (8 warps) ----
    __shared__ float wsum[8];
#pragma unroll
    for (int o = 16; o; o >>= 1) local += __shfl_xor_sync(0xFFFFFFFFu, local, o);
    if ((t & 31) == 0) wsum[t >> 5] = local;
    __syncthreads();
    if (t < 8) {
        float v = wsum[t];
#pragma unroll
        for (int o = 4; o; o >>= 1) v += __shfl_xor_sync(0xFFu, v, o);
        if (t == 0) g_partials[bid] = v;
    }
}

// ---------------------------------------------------------------------------
// K2: per row, rinv = 1/sqrt(sum), out = sqrt(m2) * rinv.  16MB traffic.
// ---------------------------------------------------------------------------
__global__ __launch_bounds__(1024) void k_scale(float* __restrict__ out) {
    const int row = blockIdx.x;
    const int t   = threadIdx.x;
    __shared__ float rinv_s;
    if (t == 0) {
        float s = g_partials[row * 4 + 0] + g_partials[row * 4 + 1]
                + g_partials[row * 4 + 2] + g_partials[row * 4 + 3];
        rinv_s = 1.0f / sqrtf(s);
    }
    __syncthreads();
    const float rinv = rinv_s;
    float4* o4 = reinterpret_cast<float4*>(out) + row * 2048;
#pragma unroll
    for (int k = 0; k < 2; k++) {
        float4 v = o4[t + 1024 * k];
        v.x = sqrtf(v.x) * rinv;
        v.y = sqrtf(v.y) * rinv;
        v.z = sqrtf(v.z) * rinv;
        v.w = sqrtf(v.w) * rinv;
        o4[t + 1024 * k] = v;
    }
}

// ------------------------- host-side threefry ------------------------------
static inline uint32_t h_rotl(uint32_t x, int r) { return (x << r) | (x >> (32 - r)); }
static void h_threefry(uint32_t k0, uint32_t k1, uint32_t x0, uint32_t x1,
                       uint32_t* o0, uint32_t* o1) {
    uint32_t ks2 = 0x1BD11BDAu ^ k0 ^ k1;
#define HTF(r) { x0 += x1; x1 = h_rotl(x1, (r)); x1 ^= x0; }
    x0 += k0;  x1 += k1;
    HTF(13) HTF(15) HTF(26) HTF(6)
    x0 += k1;  x1 += ks2 + 1u;
    HTF(17) HTF(29) HTF(16) HTF(24)
    x0 += ks2; x1 += k0 + 2u;
    HTF(13) HTF(15) HTF(26) HTF(6)
    x0 += k0;  x1 += k1 + 3u;
    HTF(17) HTF(29) HTF(16) HTF(24)
    x0 += k1;  x1 += ks2 + 4u;
    HTF(13) HTF(15) HTF(26) HTF(6)
    x0 += ks2; x1 += k0 + 5u;
#undef HTF
    *o0 = x0; *o1 = x1;
}

// ---------------------------------------------------------------------------
extern "C" void kernel_launch(void* const* d_in, const int* in_sizes, int n_in,
                              void* d_out, int out_size) {
    // metadata order: x (unused), rx_params, ry_params, rz_params
    const float* rx = (const float*)d_in[1];
    const float* ry = (const float*)d_in[2];
    const float* rz = (const float*)d_in[3];
    float* out = (float*)d_out;

    // foldlike split of key(42) = (0, 42) -> input-independent constants
    uint32_t kre0, kre1, kim0, kim1;
    h_threefry(0u, 42u, 0u, 0u, &kre0, &kre1);
    h_threefry(0u, 42u, 0u, 1u, &kim0, &kim1);

    k_noise<<<1024, 256>>>(rx, ry, rz, out, kre0, kre1, kim0, kim1);
    k_scale<<<256, 1024>>>(out);
}